// round 7
// baseline (speedup 1.0000x reference)
#include <cuda_runtime.h>
#include <cuda_fp16.h>
#include <cuda_bf16.h>
#include <cstdint>

#define OUT_F 11008
#define IN_F  4096
#define NGROW 32            // groups per output row (4096/128)
#define LUT_N (352256 * 16)
#define TPB   512
#define WPB   16            // warps per block
#define BLKS_PER_SM 2

// Permuted transposed x: slot = (g*4 + j)*32 + lane holds column c = g*128 + 4*lane + j
__device__ float4 g_xa[IN_F];   // batches 0-3
__device__ float4 g_xb[IN_F];   // batches 4-7

__global__ void transpose_x_kernel(const float* __restrict__ x) {
    int c = blockIdx.x * blockDim.x + threadIdx.x;
    if (c < IN_F) {
        int g = c >> 7, w = c & 127, l = w >> 2, j = w & 3;
        int slot = (g * 4 + j) * 32 + l;
        float4 a, b;
        a.x = x[0 * IN_F + c]; a.y = x[1 * IN_F + c];
        a.z = x[2 * IN_F + c]; a.w = x[3 * IN_F + c];
        b.x = x[4 * IN_F + c]; b.y = x[5 * IN_F + c];
        b.z = x[6 * IN_F + c]; b.w = x[7 * IN_F + c];
        g_xa[slot] = a; g_xb[slot] = b;
    }
}

__device__ __forceinline__ bool plaus(float v) {
    float a = fabsf(v);
    return isfinite(v) && a > 1e-4f && a < 0.25f;
}

__device__ __forceinline__ float cvtE(__half v)        { return __half2float(v); }
__device__ __forceinline__ float cvtE(__nv_bfloat16 v) { return __bfloat162float(v); }
__device__ __forceinline__ float cvtE(float v)         { return v; }

__device__ __forceinline__ unsigned long long dup2(float w) {
    unsigned long long r;
    asm("mov.b64 %0, {%1, %1};" : "=l"(r) : "f"(w));
    return r;
}
__device__ __forceinline__ void ffma2(unsigned long long& d,
                                      unsigned long long a,
                                      unsigned long long b) {
    asm("fma.rn.f32x2 %0, %1, %2, %0;" : "+l"(d) : "l"(a), "l"(b));
}

// Lean row pass: U<=2 so 2 blocks x 512 threads co-reside per SM (32 warps).
template <int U, typename E>
__device__ __forceinline__ void row_pass(
    const int* __restrict__ widx,
    const E* __restrict__ lut,
    const float* __restrict__ bias,
    float* __restrict__ out,
    int rs, int lane)
{
    const ulonglong2* __restrict__ xa = reinterpret_cast<const ulonglong2*>(g_xa);
    const ulonglong2* __restrict__ xb = reinterpret_cast<const ulonglong2*>(g_xb);

    const int4* wbase = reinterpret_cast<const int4*>(widx) + (size_t)rs * (IN_F / 4) + lane;
    const E*    lbase = lut + (size_t)rs * (NGROW * 16);

    unsigned long long acc[U][4];
#pragma unroll
    for (int u = 0; u < U; u++)
#pragma unroll
        for (int j = 0; j < 4; j++) acc[u][j] = 0ull;

    int4 nxt[U];
#pragma unroll
    for (int u = 0; u < U; u++)
        nxt[u] = __ldcs(wbase + u * (IN_F / 4));

    for (int g = 0; g < NGROW; g++) {
        int4 cur[U];
#pragma unroll
        for (int u = 0; u < U; u++) cur[u] = nxt[u];

        if (g + 1 < NGROW) {
#pragma unroll
            for (int u = 0; u < U; u++)
                nxt[u] = __ldcs(wbase + u * (IN_F / 4) + (g + 1) * 32);
        }

#pragma unroll
        for (int j = 0; j < 4; j++) {
            int xoff = (g * 4 + j) * 32 + lane;
            ulonglong2 va = __ldg(&xa[xoff]);   // L1-resident, coalesced
            ulonglong2 vb = __ldg(&xb[xoff]);
#pragma unroll
            for (int u = 0; u < U; u++) {
                int id = reinterpret_cast<const int*>(&cur[u])[j];
                float w = cvtE(__ldg(lbase + (size_t)u * (NGROW * 16) + g * 16 + id));
                unsigned long long w2 = dup2(w);
                ffma2(acc[u][0], w2, va.x);
                ffma2(acc[u][1], w2, va.y);
                ffma2(acc[u][2], w2, vb.x);
                ffma2(acc[u][3], w2, vb.y);
            }
        }
    }

    // unpack and warp-reduce
    float accf[U][8];
#pragma unroll
    for (int u = 0; u < U; u++)
#pragma unroll
        for (int j = 0; j < 4; j++) {
            unsigned int lo, hi;
            asm("mov.b64 {%0, %1}, %2;" : "=r"(lo), "=r"(hi) : "l"(acc[u][j]));
            accf[u][2 * j]     = __uint_as_float(lo);
            accf[u][2 * j + 1] = __uint_as_float(hi);
        }

#pragma unroll
    for (int off = 16; off > 0; off >>= 1)
#pragma unroll
        for (int u = 0; u < U; u++)
#pragma unroll
            for (int b = 0; b < 8; b++)
                accf[u][b] += __shfl_xor_sync(0xffffffffu, accf[u][b], off);

    if (lane == 0) {
#pragma unroll
        for (int u = 0; u < U; u++) {
            float bv = bias[rs + u];
#pragma unroll
            for (int b = 0; b < 8; b++)
                out[(size_t)b * OUT_F + rs + u] = accf[u][b] + bv;
        }
    }
}

template <typename E>
__device__ __forceinline__ void dispatch_rows(
    const int* __restrict__ widx, const E* __restrict__ lut,
    const float* __restrict__ bias, float* __restrict__ out,
    int rs, int nr, int lane)
{
    // nr is 2 or 3 for the chosen grid; keep only lean paths (U<=2)
    int r = rs;
    for (; r + 2 <= rs + nr; r += 2) row_pass<2, E>(widx, lut, bias, out, r, lane);
    if (r < rs + nr)                 row_pass<1, E>(widx, lut, bias, out, r, lane);
}

__global__ void __launch_bounds__(TPB, BLKS_PER_SM) pallet_kernel(
    const int* __restrict__ widx,
    const void* __restrict__ lut,
    const float* __restrict__ bias,
    float* __restrict__ out,
    int nwarps)
{
    __shared__ int s_mode;
    int tid = threadIdx.x, warp = tid >> 5, lane = tid & 31;

    // inline dtype probe (warp 0, 64 samples): how was the fp16 LUT materialized?
    if (warp == 0) {
        const unsigned short* s = (const unsigned short*)lut;
        const float* f = (const float*)lut;
        int ch = 0, cb = 0, cf = 0;
        for (int t = lane; t < 64; t += 32) {
            unsigned short v = s[t];
            if (plaus(__half2float(__ushort_as_half(v)))) ch++;
            if (plaus(__uint_as_float(((unsigned)v) << 16))) cb++;   // bf16 -> f32
            if (plaus(f[t])) cf++;
        }
#pragma unroll
        for (int o = 16; o > 0; o >>= 1) {
            ch += __shfl_xor_sync(0xffffffffu, ch, o);
            cb += __shfl_xor_sync(0xffffffffu, cb, o);
            cf += __shfl_xor_sync(0xffffffffu, cf, o);
        }
        if (lane == 0) {
            int m = 0, best = ch;
            if (cb > best) { best = cb; m = 1; }
            if (cf > best) { best = cf; m = 2; }
            s_mode = m;
        }
    }
    __syncthreads();
    int mode = s_mode;

    int w = blockIdx.x * WPB + warp;
    long long s = ((long long)w * OUT_F) / nwarps;
    long long e = ((long long)(w + 1) * OUT_F) / nwarps;
    int rs = (int)s;
    int nr = (int)(e - s);

    if (mode == 0)
        dispatch_rows<__half>(widx, (const __half*)lut, bias, out, rs, nr, lane);
    else if (mode == 1)
        dispatch_rows<__nv_bfloat16>(widx, (const __nv_bfloat16*)lut, bias, out, rs, nr, lane);
    else
        dispatch_rows<float>(widx, (const float*)lut, bias, out, rs, nr, lane);
}

extern "C" void kernel_launch(void* const* d_in, const int* in_sizes, int n_in,
                              void* d_out, int out_size) {
    // Bind inputs by element count (all four distinct):
    //   x: 32768, weight_indices: 45088768, lut: 5636096, bias: 11008
    const float* x    = nullptr;
    const int*   widx = nullptr;
    const void*  lut  = nullptr;
    const float* bias = nullptr;

    for (int i = 0; i < n_in; i++) {
        long long n = in_sizes[i];
        if (n == 8LL * IN_F)                   x    = (const float*)d_in[i];
        else if (n == (long long)OUT_F * IN_F) widx = (const int*)d_in[i];
        else if (n == (long long)LUT_N)        lut  = d_in[i];
        else if (n == OUT_F)                   bias = (const float*)d_in[i];
    }
    if (!x || !widx || !lut || !bias) {
        x    = (const float*)d_in[0];
        widx = (const int*)d_in[1];
        lut  = d_in[2];
        bias = (const float*)d_in[3];
    }

    float* out = (float*)d_out;

    int dev = 0, sms = 148;
    cudaGetDevice(&dev);
    cudaDeviceGetAttribute(&sms, cudaDevAttrMultiProcessorCount, dev);

    int blocks = sms * BLKS_PER_SM;          // 2 resident blocks per SM -> 32 warps/SM
    transpose_x_kernel<<<(IN_F + 255) / 256, 256>>>(x);
    pallet_kernel<<<blocks, TPB>>>(widx, lut, bias, out, blocks * WPB);
}

// round 8
// speedup vs baseline: 1.3777x; 1.3777x over previous
#include <cuda_runtime.h>
#include <cuda_fp16.h>
#include <cuda_bf16.h>
#include <cstdint>

#define OUT_F 11008
#define IN_F  4096
#define NGROW 32            // groups per output row (4096/128)
#define LUT_N (352256 * 16)
#define TPB   512
#define WPB   16            // warps per block

// Permuted transposed x: slot = (g*4 + j)*32 + lane holds column c = g*128 + 4*lane + j
__device__ float4 g_xa[IN_F];   // batches 0-3
__device__ float4 g_xb[IN_F];   // batches 4-7

__global__ void transpose_x_kernel(const float* __restrict__ x) {
    int c = blockIdx.x * blockDim.x + threadIdx.x;
    if (c < IN_F) {
        int g = c >> 7, w = c & 127, l = w >> 2, j = w & 3;
        int slot = (g * 4 + j) * 32 + l;
        float4 a, b;
        a.x = x[0 * IN_F + c]; a.y = x[1 * IN_F + c];
        a.z = x[2 * IN_F + c]; a.w = x[3 * IN_F + c];
        b.x = x[4 * IN_F + c]; b.y = x[5 * IN_F + c];
        b.z = x[6 * IN_F + c]; b.w = x[7 * IN_F + c];
        g_xa[slot] = a; g_xb[slot] = b;
    }
}

__device__ __forceinline__ bool plaus(float v) {
    float a = fabsf(v);
    return isfinite(v) && a > 1e-4f && a < 0.25f;
}

__device__ __forceinline__ float cvtE(__half v)        { return __half2float(v); }
__device__ __forceinline__ float cvtE(__nv_bfloat16 v) { return __bfloat162float(v); }
__device__ __forceinline__ float cvtE(float v)         { return v; }

__device__ __forceinline__ unsigned long long dup2(float w) {
    unsigned long long r;
    asm("mov.b64 %0, {%1, %1};" : "=l"(r) : "f"(w));
    return r;
}
__device__ __forceinline__ void ffma2(unsigned long long& d,
                                      unsigned long long a,
                                      unsigned long long b) {
    asm("fma.rn.f32x2 %0, %1, %2, %0;" : "+l"(d) : "l"(a), "l"(b));
}
__device__ __forceinline__ void prefetchL1(const void* p) {
    asm volatile("prefetch.global.L1 [%0];" :: "l"(p));
}

// One group-step. Slot = compile-time ring slot (g % 3).
// Issues idx loads for g+2 into ring slot (Slot+2)%3 and L1-prefetches
// the g+1 LUT rows BEFORE the FFMA body, so loads overlap two bodies.
template <int Slot, int U, typename E>
__device__ __forceinline__ void group_iter(
    int g,
    int4 (&buf)[3][U > 0 ? U : 1],
    const int4* __restrict__ wbase,
    const E* __restrict__ lbase,
    const ulonglong2* __restrict__ xa,
    const ulonglong2* __restrict__ xb,
    unsigned long long (&acc)[U > 0 ? U : 1][4],
    int lane)
{
    if (g + 2 < NGROW) {
#pragma unroll
        for (int u = 0; u < U; u++)
            buf[(Slot + 2) % 3][u] = __ldcg(wbase + u * (IN_F / 4) + (g + 2) * 32);
    }
    if (g + 1 < NGROW) {
#pragma unroll
        for (int u = 0; u < U; u++)
            prefetchL1(lbase + (size_t)u * (NGROW * 16) + (g + 1) * 16);
    }

#pragma unroll
    for (int j = 0; j < 4; j++) {
        int xoff = (g * 4 + j) * 32 + lane;
        ulonglong2 va = __ldg(&xa[xoff]);   // L1-resident, coalesced
        ulonglong2 vb = __ldg(&xb[xoff]);
#pragma unroll
        for (int u = 0; u < U; u++) {
            int id = reinterpret_cast<const int*>(&buf[Slot][u])[j];
            float w = cvtE(__ldg(lbase + (size_t)u * (NGROW * 16) + g * 16 + id));
            unsigned long long w2 = dup2(w);
            ffma2(acc[u][0], w2, va.x);
            ffma2(acc[u][1], w2, va.y);
            ffma2(acc[u][2], w2, vb.x);
            ffma2(acc[u][3], w2, vb.y);
        }
    }
}

template <int U, typename E>
__device__ __forceinline__ void row_pass(
    const int* __restrict__ widx,
    const E* __restrict__ lut,
    const float* __restrict__ bias,
    float* __restrict__ out,
    int rs, int lane)
{
    const ulonglong2* __restrict__ xa = reinterpret_cast<const ulonglong2*>(g_xa);
    const ulonglong2* __restrict__ xb = reinterpret_cast<const ulonglong2*>(g_xb);

    const int4* wbase = reinterpret_cast<const int4*>(widx) + (size_t)rs * (IN_F / 4) + lane;
    const E*    lbase = lut + (size_t)rs * (NGROW * 16);

    unsigned long long acc[U][4];
#pragma unroll
    for (int u = 0; u < U; u++)
#pragma unroll
        for (int j = 0; j < 4; j++) acc[u][j] = 0ull;

    int4 buf[3][U];
    // prologue: slots 0,1 <- groups 0,1; prefetch LUT rows for group 0
#pragma unroll
    for (int u = 0; u < U; u++) {
        buf[0][u] = __ldcg(wbase + u * (IN_F / 4));
        buf[1][u] = __ldcg(wbase + u * (IN_F / 4) + 32);
        prefetchL1(lbase + (size_t)u * (NGROW * 16));
    }

    // 30 = 3*10 groups in the rolled loop (slot pattern 0,1,2 repeats), tail 30,31
#pragma unroll 1
    for (int g = 0; g < 30; g += 3) {
        group_iter<0, U, E>(g,     buf, wbase, lbase, xa, xb, acc, lane);
        group_iter<1, U, E>(g + 1, buf, wbase, lbase, xa, xb, acc, lane);
        group_iter<2, U, E>(g + 2, buf, wbase, lbase, xa, xb, acc, lane);
    }
    group_iter<0, U, E>(30, buf, wbase, lbase, xa, xb, acc, lane);
    group_iter<1, U, E>(31, buf, wbase, lbase, xa, xb, acc, lane);

    // unpack and warp-reduce
    float accf[U][8];
#pragma unroll
    for (int u = 0; u < U; u++)
#pragma unroll
        for (int j = 0; j < 4; j++) {
            unsigned int lo, hi;
            asm("mov.b64 {%0, %1}, %2;" : "=r"(lo), "=r"(hi) : "l"(acc[u][j]));
            accf[u][2 * j]     = __uint_as_float(lo);
            accf[u][2 * j + 1] = __uint_as_float(hi);
        }

#pragma unroll
    for (int off = 16; off > 0; off >>= 1)
#pragma unroll
        for (int u = 0; u < U; u++)
#pragma unroll
            for (int b = 0; b < 8; b++)
                accf[u][b] += __shfl_xor_sync(0xffffffffu, accf[u][b], off);

    if (lane == 0) {
#pragma unroll
        for (int u = 0; u < U; u++) {
            float bv = bias[rs + u];
#pragma unroll
            for (int b = 0; b < 8; b++)
                out[(size_t)b * OUT_F + rs + u] = accf[u][b] + bv;
        }
    }
}

template <typename E>
__device__ __forceinline__ void dispatch_rows(
    const int* __restrict__ widx, const E* __restrict__ lut,
    const float* __restrict__ bias, float* __restrict__ out,
    int rs, int nr, int lane)
{
    switch (nr) {
        case 4: row_pass<4, E>(widx, lut, bias, out, rs, lane); break;
        case 5: row_pass<5, E>(widx, lut, bias, out, rs, lane); break;
        case 3: row_pass<3, E>(widx, lut, bias, out, rs, lane); break;
        case 2: row_pass<2, E>(widx, lut, bias, out, rs, lane); break;
        case 1: row_pass<1, E>(widx, lut, bias, out, rs, lane); break;
        default: {
            int r = rs;
            for (; r + 4 <= rs + nr; r += 4) row_pass<4, E>(widx, lut, bias, out, r, lane);
            for (; r < rs + nr; r++)         row_pass<1, E>(widx, lut, bias, out, r, lane);
            break;
        }
    }
}

__global__ void __launch_bounds__(TPB, 1) pallet_kernel(
    const int* __restrict__ widx,
    const void* __restrict__ lut,
    const float* __restrict__ bias,
    float* __restrict__ out,
    int nwarps)
{
    __shared__ int s_mode;
    int tid = threadIdx.x, warp = tid >> 5, lane = tid & 31;

    // inline dtype probe (warp 0, 64 samples): how was the fp16 LUT materialized?
    if (warp == 0) {
        const unsigned short* s = (const unsigned short*)lut;
        const float* f = (const float*)lut;
        int ch = 0, cb = 0, cf = 0;
        for (int t = lane; t < 64; t += 32) {
            unsigned short v = s[t];
            if (plaus(__half2float(__ushort_as_half(v)))) ch++;
            if (plaus(__uint_as_float(((unsigned)v) << 16))) cb++;   // bf16 -> f32
            if (plaus(f[t])) cf++;
        }
#pragma unroll
        for (int o = 16; o > 0; o >>= 1) {
            ch += __shfl_xor_sync(0xffffffffu, ch, o);
            cb += __shfl_xor_sync(0xffffffffu, cb, o);
            cf += __shfl_xor_sync(0xffffffffu, cf, o);
        }
        if (lane == 0) {
            int m = 0, best = ch;
            if (cb > best) { best = cb; m = 1; }
            if (cf > best) { best = cf; m = 2; }
            s_mode = m;
        }
    }
    __syncthreads();
    int mode = s_mode;

    int w = blockIdx.x * WPB + warp;
    long long s = ((long long)w * OUT_F) / nwarps;
    long long e = ((long long)(w + 1) * OUT_F) / nwarps;
    int rs = (int)s;
    int nr = (int)(e - s);

    if (mode == 0)
        dispatch_rows<__half>(widx, (const __half*)lut, bias, out, rs, nr, lane);
    else if (mode == 1)
        dispatch_rows<__nv_bfloat16>(widx, (const __nv_bfloat16*)lut, bias, out, rs, nr, lane);
    else
        dispatch_rows<float>(widx, (const float*)lut, bias, out, rs, nr, lane);
}

extern "C" void kernel_launch(void* const* d_in, const int* in_sizes, int n_in,
                              void* d_out, int out_size) {
    // Bind inputs by element count (all four distinct):
    //   x: 32768, weight_indices: 45088768, lut: 5636096, bias: 11008
    const float* x    = nullptr;
    const int*   widx = nullptr;
    const void*  lut  = nullptr;
    const float* bias = nullptr;

    for (int i = 0; i < n_in; i++) {
        long long n = in_sizes[i];
        if (n == 8LL * IN_F)                   x    = (const float*)d_in[i];
        else if (n == (long long)OUT_F * IN_F) widx = (const int*)d_in[i];
        else if (n == (long long)LUT_N)        lut  = d_in[i];
        else if (n == OUT_F)                   bias = (const float*)d_in[i];
    }
    if (!x || !widx || !lut || !bias) {
        x    = (const float*)d_in[0];
        widx = (const int*)d_in[1];
        lut  = d_in[2];
        bias = (const float*)d_in[3];
    }

    float* out = (float*)d_out;

    int dev = 0, sms = 148;
    cudaGetDevice(&dev);
    cudaDeviceGetAttribute(&sms, cudaDevAttrMultiProcessorCount, dev);

    transpose_x_kernel<<<(IN_F + 255) / 256, 256>>>(x);
    pallet_kernel<<<sms, TPB>>>(widx, lut, bias, out, sms * WPB);
}